// round 10
// baseline (speedup 1.0000x reference)
#include <cuda_runtime.h>

// B=256, N=1024, D=512, K=2.
// out[row][k] = softmax_k( exp(logit_scale) * dot(x[row], tf[k]/||tf[k]||) )
// rows = 262144. Persistent 592-block kernel (1 wave, static split).
// Warp processes chunks of 4 CONSECUTIVE rows (8KB contiguous reads) and
// emits the 4 float2 results as one full 32B sector (2x STG.128) to avoid
// ECC read-modify-write on partial-sector output stores.

#define D 512
#define ROWS (256 * 1024)
#define GRID 592
#define TPB 256
#define NWARP ((GRID * TPB) / 32)      // 4736
#define NCHUNK (ROWS / 4)              // 65536 chunks of 4 rows

__global__ __launch_bounds__(TPB, 4)
void prompts_kernel(const float4* __restrict__ x,
                    const float4* __restrict__ tf,   // [2*512] floats as float4
                    const float*  __restrict__ ls,
                    float4* __restrict__ out) {      // out viewed as float4 (2 rows each)
    const int lane = threadIdx.x & 31;
    const int warp = (blockIdx.x * TPB + threadIdx.x) >> 5;
    const unsigned FULL = 0xffffffffu;

    // ---- per-warp weight setup: load tf, normalize, fold exp(logit_scale) ----
    float4 w0[4], w1[4];
    float n0 = 0.f, n1 = 0.f;
    #pragma unroll
    for (int p = 0; p < 4; p++) {
        w0[p] = tf[p * 32 + lane];           // prompt 0: floats [0,512)
        w1[p] = tf[128 + p * 32 + lane];     // prompt 1: floats [512,1024)
        n0 += w0[p].x * w0[p].x + w0[p].y * w0[p].y + w0[p].z * w0[p].z + w0[p].w * w0[p].w;
        n1 += w1[p].x * w1[p].x + w1[p].y * w1[p].y + w1[p].z * w1[p].z + w1[p].w * w1[p].w;
    }
    #pragma unroll
    for (int o = 16; o; o >>= 1) {
        n0 += __shfl_xor_sync(FULL, n0, o);
        n1 += __shfl_xor_sync(FULL, n1, o);
    }
    const float scale = __expf(ls[0]);
    const float c0 = rsqrtf(n0) * scale;
    const float c1 = rsqrtf(n1) * scale;
    #pragma unroll
    for (int p = 0; p < 4; p++) {
        w0[p].x *= c0; w0[p].y *= c0; w0[p].z *= c0; w0[p].w *= c0;
        w1[p].x *= c1; w1[p].y *= c1; w1[p].z *= c1; w1[p].w *= c1;
    }

    // ---- main loop: 4 consecutive rows per chunk, grid-stride over chunks ----
    for (int c = warp; c < NCHUNK; c += NWARP) {
        const float4* xr = x + (size_t)c * 4 * (D / 4) + lane;
        float4 resA, resB;   // lane 0: results for rows 0,1 and 2,3 of the chunk

        #pragma unroll
        for (int i = 0; i < 4; i++) {
            float s0 = 0.f, s1 = 0.f;
            const float4* xi = xr + i * (D / 4);
            #pragma unroll
            for (int p = 0; p < 4; p++) {
                float4 v = __ldcs(xi + p * 32);
                s0 = fmaf(v.x, w0[p].x, s0);
                s0 = fmaf(v.y, w0[p].y, s0);
                s0 = fmaf(v.z, w0[p].z, s0);
                s0 = fmaf(v.w, w0[p].w, s0);
                s1 = fmaf(v.x, w1[p].x, s1);
                s1 = fmaf(v.y, w1[p].y, s1);
                s1 = fmaf(v.z, w1[p].z, s1);
                s1 = fmaf(v.w, w1[p].w, s1);
            }
            #pragma unroll
            for (int o = 16; o; o >>= 1) {
                s0 += __shfl_xor_sync(FULL, s0, o);
                s1 += __shfl_xor_sync(FULL, s1, o);
            }
            // lane 0 computes softmax and stashes the pair
            float m  = fmaxf(s0, s1);
            float e0 = __expf(s0 - m);
            float e1 = __expf(s1 - m);
            float inv = __fdividef(1.f, e0 + e1);
            float p0 = e0 * inv, p1 = e1 * inv;
            if (i == 0) { resA.x = p0; resA.y = p1; }
            if (i == 1) { resA.z = p0; resA.w = p1; }
            if (i == 2) { resB.x = p0; resB.y = p1; }
            if (i == 3) { resB.z = p0; resB.w = p1; }
        }

        if (lane == 0) {
            out[(size_t)c * 2]     = resA;   // rows 4c, 4c+1
            out[(size_t)c * 2 + 1] = resB;   // rows 4c+2, 4c+3
        }
    }
}

extern "C" void kernel_launch(void* const* d_in, const int* in_sizes, int n_in,
                              void* d_out, int out_size) {
    const float* x  = (const float*)d_in[0];   // [256,1024,512] f32
    const float* tf = (const float*)d_in[1];   // [2,512] f32
    const float* ls = (const float*)d_in[2];   // [1] f32
    float4* out = (float4*)d_out;              // [262144,2] f32 viewed as float4

    prompts_kernel<<<GRID, TPB>>>((const float4*)x, (const float4*)tf, ls, out);
}

// round 12
// speedup vs baseline: 1.0363x; 1.0363x over previous
#include <cuda_runtime.h>

// B=256, N=1024, D=512, K=2.
// out[row][k] = softmax_k( exp(logit_scale) * dot(x[row], tf[k]/||tf[k]||) )
// rows = 262144. Persistent 592-block kernel (1 wave, static split),
// warp-per-row grid-stride. Proven R8 structure; K=2 softmax folded into a
// single sigmoid, streaming stores.

#define D 512
#define ROWS (256 * 1024)
#define GRID 592
#define TPB 256
#define NWARP ((GRID * TPB) / 32)   // 4736 warps

__global__ __launch_bounds__(TPB, 4)
void prompts_kernel(const float4* __restrict__ x,
                    const float4* __restrict__ tf,   // [2*512] floats as float4
                    const float*  __restrict__ ls,
                    float2* __restrict__ out) {
    const int lane = threadIdx.x & 31;
    const int warp = (blockIdx.x * TPB + threadIdx.x) >> 5;
    const unsigned FULL = 0xffffffffu;

    // ---- per-warp weight setup: load tf, normalize, fold exp(logit_scale) ----
    float4 w0[4], w1[4];
    float n0 = 0.f, n1 = 0.f;
    #pragma unroll
    for (int p = 0; p < 4; p++) {
        w0[p] = tf[p * 32 + lane];           // prompt 0: floats [0,512)
        w1[p] = tf[128 + p * 32 + lane];     // prompt 1: floats [512,1024)
        n0 += w0[p].x * w0[p].x + w0[p].y * w0[p].y + w0[p].z * w0[p].z + w0[p].w * w0[p].w;
        n1 += w1[p].x * w1[p].x + w1[p].y * w1[p].y + w1[p].z * w1[p].z + w1[p].w * w1[p].w;
    }
    #pragma unroll
    for (int o = 16; o; o >>= 1) {
        n0 += __shfl_xor_sync(FULL, n0, o);
        n1 += __shfl_xor_sync(FULL, n1, o);
    }
    const float scale = __expf(ls[0]);
    const float c0 = rsqrtf(n0) * scale;
    const float c1 = rsqrtf(n1) * scale;
    #pragma unroll
    for (int p = 0; p < 4; p++) {
        w0[p].x *= c0; w0[p].y *= c0; w0[p].z *= c0; w0[p].w *= c0;
        w1[p].x *= c1; w1[p].y *= c1; w1[p].z *= c1; w1[p].w *= c1;
    }

    // ---- main loop: warp-per-row, pointer increment, simple body ----
    const float4* xr = x + (size_t)warp * (D / 4) + lane;
    const size_t step = (size_t)NWARP * (D / 4);

    for (int r = warp; r < ROWS; r += NWARP, xr += step) {
        float s0 = 0.f, s1 = 0.f;
        #pragma unroll
        for (int p = 0; p < 4; p++) {
            float4 v = __ldcs(xr + p * 32);
            s0 = fmaf(v.x, w0[p].x, s0);
            s0 = fmaf(v.y, w0[p].y, s0);
            s0 = fmaf(v.z, w0[p].z, s0);
            s0 = fmaf(v.w, w0[p].w, s0);
            s1 = fmaf(v.x, w1[p].x, s1);
            s1 = fmaf(v.y, w1[p].y, s1);
            s1 = fmaf(v.z, w1[p].z, s1);
            s1 = fmaf(v.w, w1[p].w, s1);
        }
        #pragma unroll
        for (int o = 16; o; o >>= 1) {
            s0 += __shfl_xor_sync(FULL, s0, o);
            s1 += __shfl_xor_sync(FULL, s1, o);
        }
        if (lane == 0) {
            // K=2 softmax == sigmoid of the logit difference (numerically safe:
            // exp of a negative-or-zero magnitude ordering handled by exp itself;
            // d large positive -> e^-d underflows to 0 -> p0 = 1).
            float d  = s1 - s0;
            float e  = __expf(d);                 // e in (0, inf)
            float p0 = __fdividef(1.f, 1.f + e);  // = e^s0/(e^s0+e^s1)
            float p1 = 1.f - p0;
            __stcs(out + r, make_float2(p0, p1));
        }
    }
}

extern "C" void kernel_launch(void* const* d_in, const int* in_sizes, int n_in,
                              void* d_out, int out_size) {
    const float* x  = (const float*)d_in[0];   // [256,1024,512] f32
    const float* tf = (const float*)d_in[1];   // [2,512] f32
    const float* ls = (const float*)d_in[2];   // [1] f32
    float2* out = (float2*)d_out;              // [262144,2] f32

    prompts_kernel<<<GRID, TPB>>>((const float4*)x, (const float4*)tf, ls, out);
}